// round 1
// baseline (speedup 1.0000x reference)
#include <cuda_runtime.h>
#include <math.h>

// Problem constants (fixed by the reference setup)
#define BB   256
#define NA   24      // atoms
#define NN   23      // neighbors per atom (N-1)
#define NP   253     // pairs = NN*(NN-1)/2
#define TT   4
#define KR   16
#define KA   32
#define NF   (KR + KA)   // 48 output features
#define RCR  5.2f
#define RCA  3.5f
#define PI_F 3.14159265358979323846f
#define LOG2E 1.4426950408889634f

__device__ __forceinline__ float ex2_approx(float x) {
    float r;
    asm("ex2.approx.ftz.f32 %0, %1;" : "=f"(r) : "f"(x));
    return r;
}
__device__ __forceinline__ float lg2_approx(float x) {
    float r;
    asm("lg2.approx.ftz.f32 %0, %1;" : "=f"(r) : "f"(x));
    return r;
}

__device__ __forceinline__ int pair_offset(int r) {
    // row offset in triu_indices(NN, k=1): off(r) = r*(2*NN-1-r)/2
    return (r * (2 * NN - 1 - r)) >> 1;
}

__global__ __launch_bounds__(256, 4)
void ani_feature_kernel(const float*  __restrict__ coords,     // (B, NA, 3)
                        const int*    __restrict__ atom_types, // (NA,)
                        const float*  __restrict__ EtaR,       // (T, KR)
                        const float*  __restrict__ ShfR,
                        const float*  __restrict__ Zeta,       // (T, KA)
                        const float*  __restrict__ ShfZ,
                        const float*  __restrict__ EtaA,
                        const float*  __restrict__ ShfA,
                        float*        __restrict__ out)        // (B, NA, 48)
{
    const int site = blockIdx.x;           // b * NA + i
    const int b = site / NA;
    const int i = site - b * NA;
    const int tid = threadIdx.x;

    __shared__ float rxs[NN], rys[NN], rzs[NN];
    __shared__ float dsh[NN], fRsh[NN], fAsh[NN];
    __shared__ float4 pairdat[NP];                 // {cosT, sinT, davg, f12*f13}
    __shared__ float etaRs[KR], shfRs[KR], g2s[KR];
    __shared__ float cosAs[KA], sinAs[KA], zetas[KA], shfZs[KA], etaA2s[KA], two2s[KA];
    __shared__ float g3part[8][KA];
    __shared__ int   ti_sh;

    if (tid == 0) ti_sh = atom_types[i];
    __syncthreads();
    const int ti = ti_sh;

    // ---- Phase 1: neighbor geometry (threads 0..22) ----
    if (tid < NN) {
        const int j = (tid < i) ? tid : tid + 1;
        const float* ci = coords + (size_t)(b * NA + i) * 3;
        const float* cj = coords + (size_t)(b * NA + j) * 3;
        float rx = ci[0] - cj[0];
        float ry = ci[1] - cj[1];
        float rz = ci[2] - cj[2];
        float d  = sqrtf(rx * rx + ry * ry + rz * rz);
        rxs[tid] = rx; rys[tid] = ry; rzs[tid] = rz;
        dsh[tid] = d;
        fRsh[tid] = 0.5f * (cosf(d * (PI_F / RCR)) + 1.0f);
        fAsh[tid] = 0.5f * (cosf(d * (PI_F / RCA)) + 1.0f);
    }

    // ---- Phase 1b: parameter tables (disjoint thread ranges) ----
    if (tid >= 32 && tid < 32 + KR) {
        const int k = tid - 32;
        etaRs[k] = EtaR[ti * KR + k];
        shfRs[k] = ShfR[ti * KR + k];
        g2s[k]   = 0.0f;
    }
    if (tid >= 64 && tid < 64 + KA) {
        const int k = tid - 64;
        float a = ShfA[ti * KA + k];
        float s, c;
        sincosf(a, &s, &c);
        cosAs[k]  = c;
        sinAs[k]  = s;
        float z   = Zeta[ti * KA + k];
        zetas[k]  = z;
        two2s[k]  = exp2f(1.0f - z);
        shfZs[k]  = ShfZ[ti * KA + k];
        etaA2s[k] = EtaA[ti * KA + k] * LOG2E;
    }
    __syncthreads();

    // ---- Phase 2: radial G2 (368 items, shared atomics over 16 addrs) ----
    for (int idx = tid; idx < NN * KR; idx += blockDim.x) {
        const int j = idx >> 4;        // / KR
        const int k = idx & (KR - 1);  // % KR
        float t = dsh[j] - shfRs[k];
        atomicAdd(&g2s[k], __expf(-etaRs[k] * t * t) * fRsh[j]);
    }

    // ---- Phase 3: pair geometry (253 items) ----
    for (int p = tid; p < NP; p += blockDim.x) {
        // decode (r, c), r < c, row-major triu_indices(NN, k=1)
        float disc = sqrtf((float)((2 * NN - 1) * (2 * NN - 1) - 8 * p));
        int r = (int)(((float)(2 * NN - 1) - disc) * 0.5f);
        if (r < 0) r = 0;
        while (pair_offset(r + 1) <= p) ++r;
        while (pair_offset(r) > p)      --r;
        const int c = p - pair_offset(r) + r + 1;

        float d1 = dsh[r], d2 = dsh[c];
        float dot = rxs[r] * rxs[c] + rys[r] * rys[c] + rzs[r] * rzs[c];
        float cs = dot / (d1 * d2);
        cs = fminf(fmaxf(cs, -1.0f + 1e-7f), 1.0f - 1e-7f);
        float sn = sqrtf(fmaxf(0.0f, 1.0f - cs * cs));
        pairdat[p] = make_float4(cs, sn, 0.5f * (d1 + d2), fAsh[r] * fAsh[c]);
    }
    __syncthreads();

    // ---- Phase 4: angular G3 — warp w strides pairs, lane l = feature k ----
    {
        const int w = tid >> 5;
        const int l = tid & 31;
        const float zk  = zetas[l];
        const float cak = cosAs[l];
        const float sak = sinAs[l];
        const float sZk = shfZs[l];
        const float e2k = etaA2s[l];
        float acc = 0.0f;
        #pragma unroll 4
        for (int p = w; p < NP; p += 8) {
            float4 pd = pairdat[p];                    // broadcast LDS.128
            float cosang = fmaf(pd.x, cak, pd.y * sak);
            float lg = lg2_approx(1.0f + cosang);
            float dd = pd.z - sZk;
            float e  = fmaf(zk, lg, -e2k * dd * dd);   // zeta*log2 - etaA*log2e*dd^2
            acc = fmaf(ex2_approx(e), pd.w, acc);
        }
        g3part[w][l] = acc;
    }
    __syncthreads();

    // ---- Phase 5: reduce + write output ----
    float* osite = out + (size_t)site * NF;
    if (tid < KA) {
        float s = 0.0f;
        #pragma unroll
        for (int ww = 0; ww < 8; ++ww) s += g3part[ww][tid];
        osite[KR + tid] = two2s[tid] * s;
    }
    if (tid >= 64 && tid < 64 + KR) {
        const int k = tid - 64;
        osite[k] = g2s[k];
    }
}

extern "C" void kernel_launch(void* const* d_in, const int* in_sizes, int n_in,
                              void* d_out, int out_size) {
    const float* coords     = (const float*)d_in[0];
    const int*   atom_types = (const int*)  d_in[1];
    const float* EtaR       = (const float*)d_in[2];
    const float* ShfR       = (const float*)d_in[3];
    const float* Zeta       = (const float*)d_in[4];
    const float* ShfZ       = (const float*)d_in[5];
    const float* EtaA       = (const float*)d_in[6];
    const float* ShfA       = (const float*)d_in[7];
    float* out = (float*)d_out;

    ani_feature_kernel<<<BB * NA, 256>>>(coords, atom_types, EtaR, ShfR, Zeta,
                                         ShfZ, EtaA, ShfA, out);
}

// round 2
// speedup vs baseline: 1.1656x; 1.1656x over previous
#include <cuda_runtime.h>
#include <math.h>

// Problem constants (fixed by the reference setup)
#define BB   256
#define NA   24      // atoms
#define NN   23      // neighbors per atom (N-1)
#define NP   253     // pairs = NN*(NN-1)/2
#define KR   16
#define KA   32
#define NF   (KR + KA)   // 48 output features
#define RCR  5.2f
#define RCA  3.5f
#define PI_F 3.14159265358979323846f
#define LOG2E 1.4426950408889634f

static __device__ __forceinline__ float ex2_approx(float x) {
    float r;
    asm("ex2.approx.ftz.f32 %0, %1;" : "=f"(r) : "f"(x));
    return r;
}
static __device__ __forceinline__ float lg2_approx(float x) {
    float r;
    asm("lg2.approx.ftz.f32 %0, %1;" : "=f"(r) : "f"(x));
    return r;
}
static __device__ __forceinline__ int pair_offset(int r) {
    // row offset in triu_indices(NN, k=1): off(r) = r*(2*NN-1-r)/2
    return (r * (2 * NN - 1 - r)) >> 1;
}

__global__ __launch_bounds__(256)
void ani_feature_kernel(const float*  __restrict__ coords,     // (B, NA, 3)
                        const int*    __restrict__ atom_types, // (NA,)
                        const float*  __restrict__ EtaR,       // (T, KR)
                        const float*  __restrict__ ShfR,
                        const float*  __restrict__ Zeta,       // (T, KA)
                        const float*  __restrict__ ShfZ,
                        const float*  __restrict__ EtaA,
                        const float*  __restrict__ ShfA,
                        float*        __restrict__ out)        // (B, NA, 48)
{
    const int site = blockIdx.x;           // b * NA + i
    const int b = site / NA;
    const int i = site - b * NA;
    const int tid = threadIdx.x;

    __shared__ float rxs[NN], rys[NN], rzs[NN];
    __shared__ float dsh[NN], fRsh[NN], fAsh[NN];
    __shared__ float etaRs[KR], shfRs[KR], g2s[KR];
    __shared__ float cosAs[KA], sinAs[KA], zetas[KA], shfZs[KA], etaA2s[KA], two2s[KA];
    // Fast-path per-pair specials (padded to 256 pairs):
    __shared__ float pow4[256 * 4];                 // (1+cos(theta-a))^zeta, a = k/8
    __shared__ __align__(16) float radf8[256 * 8];  // exp(-etaA*(davg-s_z)^2)*f12f13, z = k%8
    __shared__ float g3part[8][KA];
    __shared__ int   ti_sh;
    __shared__ int   sflag;   // 1 if the 8x4 outer-product structure holds

    if (tid == 0) { ti_sh = atom_types[i]; sflag = 1; }
    __syncthreads();
    const int ti = ti_sh;

    // ---- Phase 1: neighbor geometry (threads 0..22) ----
    if (tid < NN) {
        const int j = (tid < i) ? tid : tid + 1;
        const float* ci = coords + (size_t)(b * NA + i) * 3;
        const float* cj = coords + (size_t)(b * NA + j) * 3;
        float rx = ci[0] - cj[0];
        float ry = ci[1] - cj[1];
        float rz = ci[2] - cj[2];
        float d  = sqrtf(rx * rx + ry * ry + rz * rz);
        rxs[tid] = rx; rys[tid] = ry; rzs[tid] = rz;
        dsh[tid] = d;
        fRsh[tid] = 0.5f * (cosf(d * (PI_F / RCR)) + 1.0f);
        fAsh[tid] = 0.5f * (cosf(d * (PI_F / RCA)) + 1.0f);
    }

    // ---- Phase 1b: parameter tables + structure check ----
    if (tid >= 32 && tid < 32 + KR) {
        const int k = tid - 32;
        etaRs[k] = EtaR[ti * KR + k];
        shfRs[k] = ShfR[ti * KR + k];
        g2s[k]   = 0.0f;
    }
    if (tid >= 64 && tid < 64 + KA) {
        const int k = tid - 64;
        float a = ShfA[ti * KA + k];
        float s, c;
        sincosf(a, &s, &c);
        cosAs[k]  = c;
        sinAs[k]  = s;
        float z   = Zeta[ti * KA + k];
        zetas[k]  = z;
        two2s[k]  = exp2f(1.0f - z);
        shfZs[k]  = ShfZ[ti * KA + k];
        etaA2s[k] = -EtaA[ti * KA + k] * LOG2E;   // stored negated
        // Structure: ShfZ/EtaA depend only on k%8; ShfA/Zeta only on k/8
        bool ok = (ShfZ[ti * KA + k] == ShfZ[ti * KA + (k & 7)]) &&
                  (EtaA[ti * KA + k] == EtaA[ti * KA + (k & 7)]) &&
                  (ShfA[ti * KA + k] == ShfA[ti * KA + (k & ~7)]) &&
                  (Zeta[ti * KA + k] == Zeta[ti * KA + (k & ~7)]);
        if (!ok) sflag = 0;
    }
    __syncthreads();

    const int structured = sflag;

    // ---- Phase 2: radial G2 (368 items, shared atomics over 16 addrs) ----
    for (int idx = tid; idx < NN * KR; idx += 256) {
        const int j = idx >> 4;        // / KR
        const int k = idx & (KR - 1);  // % KR
        float t = dsh[j] - shfRs[k];
        atomicAdd(&g2s[k], __expf(-etaRs[k] * t * t) * fRsh[j]);
    }

    // ---- Phase 3: pair geometry + per-pair specials (1 thread = 1 pair) ----
    {
        const int p = tid;                 // 0..255, pairs 253..255 are padding
        float cs = 1.0f, sn = 0.0f, dz = 0.0f, fw = 0.0f;
        if (p < NP) {
            // decode (r, c), r < c, row-major triu_indices(NN, k=1)
            float disc = sqrtf((float)((2 * NN - 1) * (2 * NN - 1) - 8 * p));
            int r = (int)(((float)(2 * NN - 1) - disc) * 0.5f);
            if (r < 0) r = 0;
            while (pair_offset(r + 1) <= p) ++r;
            while (pair_offset(r) > p)      --r;
            const int c = p - pair_offset(r) + r + 1;

            float d1 = dsh[r], d2 = dsh[c];
            float dot = rxs[r] * rxs[c] + rys[r] * rys[c] + rzs[r] * rzs[c];
            cs = dot / (d1 * d2);
            cs = fminf(fmaxf(cs, -1.0f + 1e-7f), 1.0f - 1e-7f);
            sn = sqrtf(fmaxf(0.0f, 1.0f - cs * cs));
            dz = 0.5f * (d1 + d2);
            fw = fAsh[r] * fAsh[c];
        }
        if (structured) {
            #pragma unroll
            for (int a = 0; a < 4; ++a) {
                float cang = fmaf(cs, cosAs[a * 8], sn * sinAs[a * 8]);
                pow4[p * 4 + a] = ex2_approx(zetas[a * 8] * lg2_approx(1.0f + cang));
            }
            #pragma unroll
            for (int z = 0; z < 8; ++z) {
                float dd = dz - shfZs[z];
                radf8[p * 8 + z] = ex2_approx((etaA2s[z] * dd) * dd) * fw;
            }
        } else {
            // Fallback layout reuses radf8 storage as float4 pairdat[256]
            reinterpret_cast<float4*>(radf8)[p] = make_float4(cs, sn, dz, fw);
        }
    }
    __syncthreads();

    // ---- Phase 4: angular accumulation ----
    {
        const int w = tid >> 5;
        const int l = tid & 31;
        float acc = 0.0f;
        if (structured) {
            // feature l = (a = l/8, z = l%8); warp w covers pairs p = w + 8t
            const float* pp = pow4  + (w * 4 + (l >> 3));
            const float* rp = radf8 + (w * 8 + (l & 7));
            #pragma unroll
            for (int t = 0; t < 32; ++t)
                acc = fmaf(pp[t * 32], rp[t * 64], acc);     // 2 LDS + 1 FFMA per pair
        } else {
            const float4* pairdat = reinterpret_cast<const float4*>(radf8);
            const float zk  = zetas[l];
            const float cak = cosAs[l];
            const float sak = sinAs[l];
            const float sZk = shfZs[l];
            const float e2k = etaA2s[l];   // negative
            #pragma unroll 4
            for (int p = w; p < 256; p += 8) {
                float4 pd = pairdat[p];
                float cosang = fmaf(pd.x, cak, pd.y * sak);
                float lg = lg2_approx(1.0f + cosang);
                float dd = pd.z - sZk;
                float e  = fmaf(zk, lg, (e2k * dd) * dd);
                acc = fmaf(ex2_approx(e), pd.w, acc);
            }
        }
        g3part[w][l] = acc;
    }
    __syncthreads();

    // ---- Phase 5: reduce + write output ----
    float* osite = out + (size_t)site * NF;
    if (tid < KA) {
        float s = 0.0f;
        #pragma unroll
        for (int ww = 0; ww < 8; ++ww) s += g3part[ww][tid];
        osite[KR + tid] = two2s[tid] * s;
    }
    if (tid >= 64 && tid < 64 + KR) {
        const int k = tid - 64;
        osite[k] = g2s[k];
    }
}

extern "C" void kernel_launch(void* const* d_in, const int* in_sizes, int n_in,
                              void* d_out, int out_size) {
    const float* coords     = (const float*)d_in[0];
    const int*   atom_types = (const int*)  d_in[1];
    const float* EtaR       = (const float*)d_in[2];
    const float* ShfR       = (const float*)d_in[3];
    const float* Zeta       = (const float*)d_in[4];
    const float* ShfZ       = (const float*)d_in[5];
    const float* EtaA       = (const float*)d_in[6];
    const float* ShfA       = (const float*)d_in[7];
    float* out = (float*)d_out;

    ani_feature_kernel<<<BB * NA, 256>>>(coords, atom_types, EtaR, ShfR, Zeta,
                                         ShfZ, EtaA, ShfA, out);
}

// round 6
// speedup vs baseline: 1.5058x; 1.2919x over previous
#include <cuda_runtime.h>
#include <math.h>

// Problem constants (fixed by the reference setup)
#define BB   256
#define NA   24      // atoms
#define NN   23      // neighbors per atom (N-1)
#define NP   253     // pairs = NN*(NN-1)/2
#define KR   16
#define KA   32
#define NF   (KR + KA)
#define RCR  5.2f
#define RCA  3.5f
#define PI_F 3.14159265358979323846f
#define LOG2E 1.4426950408889634f

#define PSTR 264     // pow_t row stride in floats (264 % 32 == 8  -> staggered banks)
#define RSTR 260     // radf_t row stride in floats (260 % 32 == 4 -> staggered banks)
#define SCALE_UP 100.0f
#define SCALE_DN 7.888609052210118e-31f   // 2^-100

static __device__ __forceinline__ float ex2_approx(float x) {
    float r;
    asm("ex2.approx.ftz.f32 %0, %1;" : "=f"(r) : "f"(x));
    return r;
}
static __device__ __forceinline__ float lg2_approx(float x) {
    float r;
    asm("lg2.approx.ftz.f32 %0, %1;" : "=f"(r) : "f"(x));
    return r;
}

// Compile-time pair table: pair p -> (r | c<<8), rows of triu_indices(NN, k=1)
struct PT { unsigned short v[256]; };
static constexpr PT make_pt() {
    PT t{};
    int p = 0;
    for (int r = 0; r < NN; ++r)
        for (int c = r + 1; c < NN; ++c) { t.v[p] = (unsigned short)(r | (c << 8)); ++p; }
    for (; p < 256; ++p) t.v[p] = (unsigned short)(0 | (1 << 8));  // padding pairs
    return t;
}
static __device__ const PT d_pt = make_pt();

__global__ __launch_bounds__(256)
void ani_feature_kernel(const float*  __restrict__ coords,     // (B, NA, 3)
                        const int*    __restrict__ atom_types, // (NA,)
                        const float*  __restrict__ EtaR,       // (T, KR)
                        const float*  __restrict__ ShfR,
                        const float*  __restrict__ Zeta,       // (T, KA)
                        const float*  __restrict__ ShfZ,
                        const float*  __restrict__ EtaA,
                        const float*  __restrict__ ShfA,
                        float*        __restrict__ out)        // (B, NA, 48)
{
    const int site = blockIdx.x;           // b * NA + i
    const int b = site / NA;
    const int i = site - b * NA;
    const int tid = threadIdx.x;
    const int w = tid >> 5;
    const int l = tid & 31;

    __shared__ float rxs[NN], rys[NN], rzs[NN];
    __shared__ float dsh[NN], invd[NN], fRsh[NN], fAsh[NN];
    __shared__ float etaRs[KR], shfRs[KR];
    __shared__ float cosAs[KA], sinAs[KA], zetas[KA], shfZs[KA], etaA2s[KA], two2s[KA];
    __shared__ float ratioz[7];
    __shared__ float s0c, eAc, c1c;
    __shared__ float g2part[8][KR];
    __shared__ float g3part[8][KA];
    __shared__ __align__(16) float pow_t[4 * PSTR];   // (1+cos(theta-a))^zeta, row a
    __shared__ __align__(16) float radf_t[8 * RSTR];  // exp(-eta(dz-s_z)^2)*fw,  row z
    __shared__ int ti_sh, sflag;

    if (tid == 0) { ti_sh = atom_types[i]; sflag = 1; }
    __syncthreads();
    const int ti = ti_sh;

    // ---- Phase 1: neighbor geometry (threads 0..22) ----
    if (tid < NN) {
        const int j = (tid < i) ? tid : tid + 1;
        const float* ci = coords + (size_t)(b * NA + i) * 3;
        const float* cj = coords + (size_t)(b * NA + j) * 3;
        float rx = ci[0] - cj[0];
        float ry = ci[1] - cj[1];
        float rz = ci[2] - cj[2];
        float d  = sqrtf(rx * rx + ry * ry + rz * rz);
        rxs[tid] = rx; rys[tid] = ry; rzs[tid] = rz;
        dsh[tid] = d;
        invd[tid] = __frcp_rn(d);
        fRsh[tid] = 0.5f * (cosf(d * (PI_F / RCR)) + 1.0f);
        fAsh[tid] = 0.5f * (cosf(d * (PI_F / RCA)) + 1.0f);
    }

    // ---- Phase 1b: parameter tables + fast-path structure checks ----
    if (tid >= 32 && tid < 32 + KR) {
        const int k = tid - 32;
        etaRs[k] = EtaR[ti * KR + k];
        shfRs[k] = ShfR[ti * KR + k];
    }
    if (tid >= 64 && tid < 64 + KA) {
        const int k = tid - 64;
        float a = ShfA[ti * KA + k];
        float s, c;
        sincosf(a, &s, &c);
        cosAs[k]  = c;
        sinAs[k]  = s;
        float z   = Zeta[ti * KA + k];
        zetas[k]  = z;
        two2s[k]  = exp2f(1.0f - z);
        shfZs[k]  = ShfZ[ti * KA + k];
        etaA2s[k] = -EtaA[ti * KA + k] * LOG2E;

        // Fast-path requirements:
        //  zeta == 32 everywhere; EtaA uniform; ShfA depends only on k/8;
        //  ShfZ is (approximately) a uniform grid depending only on k%8.
        float sz0  = ShfZ[ti * KA];
        float dlt  = (ShfZ[ti * KA + 7] - sz0) * (1.0f / 7.0f);
        bool ok = (z == 32.0f)
               && (EtaA[ti * KA + k] == EtaA[ti * KA])
               && (ShfA[ti * KA + k] == ShfA[ti * KA + (k & ~7)])
               && (ShfZ[ti * KA + k] == ShfZ[ti * KA + (k & 7)])
               && (fabsf(ShfZ[ti * KA + (k & 7)] - (sz0 + (float)(k & 7) * dlt)) < 1e-4f);
        if (!ok) sflag = 0;
    }
    if (tid >= 96 && tid < 96 + 7) {
        const int z = tid - 96;
        float sz0 = ShfZ[ti * KA];
        float dlt = (ShfZ[ti * KA + 7] - sz0) * (1.0f / 7.0f);
        float eA  = EtaA[ti * KA] * LOG2E;
        ratioz[z] = exp2f(-eA * dlt * dlt * (float)(2 * z + 1));
    }
    if (tid == 103) {
        float sz0 = ShfZ[ti * KA];
        float dlt = (ShfZ[ti * KA + 7] - sz0) * (1.0f / 7.0f);
        s0c = sz0;
        eAc = EtaA[ti * KA] * LOG2E;
        c1c = 2.0f * EtaA[ti * KA] * dlt * LOG2E;
    }
    __syncthreads();

    const int fast = sflag;

    // ---- Phase 2: radial G2 (per-warp partials, no atomics) ----
    if (l < KR) {
        float acc2 = 0.0f;
        for (int j = w; j < NN; j += 8) {
            float t = dsh[j] - shfRs[l];
            acc2 += __expf(-etaRs[l] * t * t) * fRsh[j];
        }
        g2part[w][l] = acc2;
    }

    // ---- Phase 3: per-pair geometry + specials (1 thread = 1 pair) ----
    {
        const int p = tid;                          // 0..255; 253..255 padding (fw = 0)
        const unsigned short rc = d_pt.v[p];
        const int r = rc & 0xFF, c = rc >> 8;
        float d1 = dsh[r], d2 = dsh[c];
        float dot = rxs[r] * rxs[c] + rys[r] * rys[c] + rzs[r] * rzs[c];
        float cs = dot * invd[r] * invd[c];
        cs = fminf(fmaxf(cs, -1.0f + 1e-7f), 1.0f - 1e-7f);
        float sn = sqrtf(fmaxf(0.0f, 1.0f - cs * cs));
        float dz = 0.5f * (d1 + d2);
        float fw = (p < NP) ? fAsh[r] * fAsh[c] : 0.0f;

        if (fast) {
            // 4 angular powers: (1 + cos(theta - a))^32 via 5 squarings (no MUFU)
            #pragma unroll
            for (int a = 0; a < 4; ++a) {
                float x  = 1.0f + fmaf(cs, cosAs[a * 8], sn * sinAs[a * 8]);
                float x2 = x * x, x4 = x2 * x2, x8 = x4 * x4, x16 = x8 * x8;
                pow_t[a * PSTR + p] = x16 * x16;
            }
            // 8 radial envelopes via 2^100-scaled geometric ladder (2 MUFU total)
            float u = dz - s0c;
            float A = ex2_approx(fmaf(-eAc * u, u, SCALE_UP));
            float R = ex2_approx(c1c * u);
            float unsc = fw * SCALE_DN;
            float v = A;
            radf_t[p] = v * unsc;
            #pragma unroll
            for (int z = 0; z < 7; ++z) {
                v *= R * ratioz[z];
                radf_t[(z + 1) * RSTR + p] = v * unsc;
            }
        } else {
            reinterpret_cast<float4*>(radf_t)[p] = make_float4(cs, sn, dz, fw);
        }
    }
    __syncthreads();

    // ---- Phase 4: angular accumulation ----
    {
        float acc = 0.0f;
        if (fast) {
            // lane l = feature (a = l/8, z = l%8); warp w covers pairs [32w, 32w+32)
            const float4* pp = reinterpret_cast<const float4*>(pow_t  + (l >> 3) * PSTR) + w * 8;
            const float4* rp = reinterpret_cast<const float4*>(radf_t + (l & 7)  * RSTR) + w * 8;
            #pragma unroll
            for (int t = 0; t < 8; ++t) {
                float4 P = pp[t];
                float4 Q = rp[t];
                acc = fmaf(P.x, Q.x, acc);
                acc = fmaf(P.y, Q.y, acc);
                acc = fmaf(P.z, Q.z, acc);
                acc = fmaf(P.w, Q.w, acc);
            }
        } else {
            const float4* pairdat = reinterpret_cast<const float4*>(radf_t);
            const float zk  = zetas[l];
            const float cak = cosAs[l];
            const float sak = sinAs[l];
            const float sZk = shfZs[l];
            const float e2k = etaA2s[l];   // negative
            #pragma unroll 4
            for (int p = w; p < 256; p += 8) {
                float4 pd = pairdat[p];
                float cosang = fmaf(pd.x, cak, pd.y * sak);
                float lg = lg2_approx(1.0f + cosang);
                float dd = pd.z - sZk;
                float e  = fmaf(zk, lg, (e2k * dd) * dd);
                acc = fmaf(ex2_approx(e), pd.w, acc);
            }
        }
        g3part[w][l] = acc;
    }
    __syncthreads();

    // ---- Phase 5: reduce + write output ----
    float* osite = out + (size_t)site * NF;
    if (tid < KA) {
        float s = 0.0f;
        #pragma unroll
        for (int ww = 0; ww < 8; ++ww) s += g3part[ww][tid];
        osite[KR + tid] = two2s[tid] * s;
    }
    if (tid >= 64 && tid < 64 + KR) {
        const int k = tid - 64;
        float s = 0.0f;
        #pragma unroll
        for (int ww = 0; ww < 8; ++ww) s += g2part[ww][k];
        osite[k] = s;
    }
}

extern "C" void kernel_launch(void* const* d_in, const int* in_sizes, int n_in,
                              void* d_out, int out_size) {
    const float* coords     = (const float*)d_in[0];
    const int*   atom_types = (const int*)  d_in[1];
    const float* EtaR       = (const float*)d_in[2];
    const float* ShfR       = (const float*)d_in[3];
    const float* Zeta       = (const float*)d_in[4];
    const float* ShfZ       = (const float*)d_in[5];
    const float* EtaA       = (const float*)d_in[6];
    const float* ShfA       = (const float*)d_in[7];
    float* out = (float*)d_out;

    ani_feature_kernel<<<BB * NA, 256>>>(coords, atom_types, EtaR, ShfR, Zeta,
                                         ShfZ, EtaA, ShfA, out);
}